// round 4
// baseline (speedup 1.0000x reference)
#include <cuda_runtime.h>
#include <cfloat>

#define N_EMBED  8192
#define E_DIM    64
#define N_QUERY  16384
#define QT       64
#define CT       128
#define NTHREADS 256
#define QSTRIDE  66   // row stride (floats) for smem tiles: odd-ish stride kills bank conflicts

__device__ float g_norms[N_EMBED];

// ||e_j||^2 for every code. embed is [E_DIM, N_EMBED] row-major -> coalesced over j.
__global__ void __launch_bounds__(256) norms_kernel(const float* __restrict__ embed) {
    int j = blockIdx.x * 256 + threadIdx.x;
    float s = 0.f;
#pragma unroll
    for (int d = 0; d < E_DIM; ++d) {
        float v = embed[d * N_EMBED + j];
        s = fmaf(v, v, s);
    }
    g_norms[j] = s;
}

// Packed fp32x2 FMA (Blackwell 2x-FP32 path; only reachable via PTX).
__device__ __forceinline__ unsigned long long ffma2(unsigned long long a,
                                                    unsigned long long b,
                                                    unsigned long long c) {
    unsigned long long d;
    asm("fma.rn.f32x2 %0, %1, %2, %3;" : "=l"(d) : "l"(a), "l"(b), "l"(c));
    return d;
}

__global__ void __launch_bounds__(NTHREADS, 2) vq_kernel(
    const float* __restrict__ x,      // [16, 64, 32, 32] NCHW
    const float* __restrict__ embed,  // [64, 8192]
    float* __restrict__ out)          // [16, 32, 32, 64]
{
    extern __shared__ float smem[];
    float* sQ    = smem;                     // [QT][QSTRIDE], query-major (q, k)
    float* sE    = smem + QT * QSTRIDE;      // [CT][QSTRIDE], code-major  (j, k)
    int*   sBest = (int*)(sE + CT * QSTRIDE);

    const int tid = threadIdx.x;
    const int cg  = tid & 15;   // column group: codes j = cbase + cg + 16*p
    const int rg  = tid >> 4;   // row group:    queries rg*4 .. rg*4+3
    const int q0  = blockIdx.x * QT;
    const int b   = q0 >> 10;        // batch index (tiles never straddle a batch: 1024 % 64 == 0)
    const int hw0 = q0 & 1023;

    // ---- load Q tile (transpose NCHW slab -> [q][k]) ----
#pragma unroll
    for (int it = 0; it < (QT * E_DIM) / NTHREADS; ++it) {
        int idx = tid + it * NTHREADS;
        int d = idx >> 6;
        int q = idx & 63;
        sQ[q * QSTRIDE + d] = x[(size_t)b * 65536 + d * 1024 + hw0 + q];
    }

    float bestS[4];
    int   bestJ[4];
#pragma unroll
    for (int i = 0; i < 4; ++i) { bestS[i] = FLT_MAX; bestJ[i] = 0; }

    for (int cbase = 0; cbase < N_EMBED; cbase += CT) {
        __syncthreads();  // sQ visible (iter 0) / previous sE reads done
        // ---- load E tile [CT codes][E_DIM], code-major ----
#pragma unroll
        for (int it = 0; it < (CT * E_DIM) / NTHREADS; ++it) {
            int idx = tid + it * NTHREADS;
            int d = idx >> 7;
            int j = idx & 127;
            sE[j * QSTRIDE + d] = embed[d * N_EMBED + cbase + j];
        }
        __syncthreads();

        // ---- 4x8 micro-tile dot products, packed over (even k, odd k) ----
        unsigned long long acc[4][8];
#pragma unroll
        for (int i = 0; i < 4; ++i)
#pragma unroll
            for (int p = 0; p < 8; ++p) acc[i][p] = 0ULL;

#pragma unroll 4
        for (int kk = 0; kk < E_DIM; kk += 2) {
            unsigned long long qp[4];
#pragma unroll
            for (int i = 0; i < 4; ++i)
                qp[i] = *(const unsigned long long*)(sQ + (rg * 4 + i) * QSTRIDE + kk);
#pragma unroll
            for (int p = 0; p < 8; ++p) {
                unsigned long long ep =
                    *(const unsigned long long*)(sE + (cg + 16 * p) * QSTRIDE + kk);
#pragma unroll
                for (int i = 0; i < 4; ++i)
                    acc[i][p] = ffma2(qp[i], ep, acc[i][p]);
            }
        }

        // ---- chunk epilogue: score = ||e||^2 - 2*dot, running argmin ----
#pragma unroll
        for (int p = 0; p < 8; ++p) {
            int j = cbase + cg + 16 * p;
            float nj = g_norms[j];
#pragma unroll
            for (int i = 0; i < 4; ++i) {
                float lo, hi;
                asm("mov.b64 {%0,%1}, %2;" : "=f"(lo), "=f"(hi) : "l"(acc[i][p]));
                float dot = lo + hi;
                float score = fmaf(-2.f, dot, nj);
                if (score < bestS[i] || (score == bestS[i] && j < bestJ[i])) {
                    bestS[i] = score;
                    bestJ[i] = j;
                }
            }
        }
    }

    // ---- reduce across the 16 cg lanes (half-warp groups, width 16) ----
#pragma unroll
    for (int i = 0; i < 4; ++i) {
#pragma unroll
        for (int off = 8; off > 0; off >>= 1) {
            float os = __shfl_down_sync(0xFFFFFFFFu, bestS[i], off, 16);
            int   oj = __shfl_down_sync(0xFFFFFFFFu, bestJ[i], off, 16);
            if (os < bestS[i] || (os == bestS[i] && oj < bestJ[i])) {
                bestS[i] = os;
                bestJ[i] = oj;
            }
        }
    }
    if (cg == 0) {
#pragma unroll
        for (int i = 0; i < 4; ++i) sBest[rg * 4 + i] = bestJ[i];
    }
    __syncthreads();

    // ---- gather winning codes, coalesced store ----
#pragma unroll
    for (int it = 0; it < (QT * E_DIM) / NTHREADS; ++it) {
        int idx = tid + it * NTHREADS;
        int q = idx >> 6;
        int d = idx & 63;
        int j = sBest[q];
        out[(size_t)(q0 + q) * E_DIM + d] = embed[d * N_EMBED + j];
    }
}

extern "C" void kernel_launch(void* const* d_in, const int* in_sizes, int n_in,
                              void* d_out, int out_size) {
    const float* x     = (const float*)d_in[0];   // 16*64*32*32 = 1048576
    const float* embed = (const float*)d_in[1];   // 64*8192    =  524288
    float* out = (float*)d_out;                   // 16*32*32*64 fp32

    norms_kernel<<<N_EMBED / 256, 256>>>(embed);

    size_t smem_bytes = (size_t)(QT * QSTRIDE + CT * QSTRIDE) * sizeof(float)
                      + (size_t)QT * sizeof(int);
    cudaFuncSetAttribute(vq_kernel, cudaFuncAttributeMaxDynamicSharedMemorySize,
                         (int)smem_bytes);
    vq_kernel<<<N_QUERY / QT, NTHREADS, smem_bytes>>>(x, embed, out);
}

// round 6
// speedup vs baseline: 1.5799x; 1.5799x over previous
#include <cuda_runtime.h>
#include <cuda_bf16.h>
#include <cfloat>
#include <cstdint>

#define N_EMBED  8192
#define E_DIM    64
#define N_QUERY  16384
#define MT       128                 // queries per CTA
#define NT       128                 // codes per chunk
#define NCHUNK   (N_EMBED / NT)      // 64
#define CAND_MAX 160
#define MARGIN   0.5f

// ---------------- global scratch ----------------
__device__ float          g_norms[N_EMBED];
__device__ float          g_embT [N_EMBED * E_DIM];   // [code][k] fp32 (exact)
__device__ __nv_bfloat16  g_ebf16[N_EMBED * E_DIM];   // [code][k] bf16
__device__ float          g_xq   [N_QUERY * E_DIM];   // [q][k] fp32
__device__ __nv_bfloat16  g_xbf16[N_QUERY * E_DIM];   // [q][k] bf16
__device__ int            g_cand [N_QUERY * CAND_MAX];
__device__ int            g_ncand[N_QUERY];

// ---------------- PTX helpers (family-safe: sm_80+ only) ----------------
__device__ __forceinline__ uint32_t smem_u32(const void* p) {
    uint32_t a;
    asm("{ .reg .u64 t; cvta.to.shared.u64 t, %1; cvt.u32.u64 %0, t; }" : "=r"(a) : "l"(p));
    return a;
}
#define SWZ128(o) ((o) ^ (((o) >> 3) & 0x70))

#define CP_ASYNC16(dst, src) \
    asm volatile("cp.async.cg.shared.global [%0], [%1], 16;" :: "r"(dst), "l"(src) : "memory")
#define CP_COMMIT() asm volatile("cp.async.commit_group;" ::: "memory")
#define CP_WAIT1()  asm volatile("cp.async.wait_group 1;" ::: "memory")

#define LDSM_X4(r0, r1, r2, r3, addr) \
    asm volatile("ldmatrix.sync.aligned.m8n8.x4.shared.b16 {%0,%1,%2,%3}, [%4];" \
                 : "=r"(r0), "=r"(r1), "=r"(r2), "=r"(r3) : "r"(addr))

__device__ __forceinline__ void mma16816(float* c, const uint32_t* a, const uint32_t* b) {
    asm volatile(
        "mma.sync.aligned.m16n8k16.row.col.f32.bf16.bf16.f32 "
        "{%0,%1,%2,%3}, {%4,%5,%6,%7}, {%8,%9}, {%0,%1,%2,%3};"
        : "+f"(c[0]), "+f"(c[1]), "+f"(c[2]), "+f"(c[3])
        : "r"(a[0]), "r"(a[1]), "r"(a[2]), "r"(a[3]), "r"(b[0]), "r"(b[1]));
}

// ---------------- prep kernels ----------------
__global__ void __launch_bounds__(256) norms_kernel(const float* __restrict__ embed) {
    int j = blockIdx.x * 256 + threadIdx.x;
    float s = 0.f;
#pragma unroll
    for (int d = 0; d < E_DIM; ++d) {
        float v = embed[d * N_EMBED + j];
        s = fmaf(v, v, s);
    }
    g_norms[j] = s;
}

__global__ void __launch_bounds__(256) tr_e_kernel(const float* __restrict__ embed) {
    __shared__ float s[64][33];
    int j0 = blockIdx.x * 32;
    int t = threadIdx.x;
#pragma unroll
    for (int it = 0; it < 8; ++it) {
        int idx = t + it * 256;
        int d = idx >> 5, jj = idx & 31;
        s[d][jj] = embed[d * N_EMBED + j0 + jj];
    }
    __syncthreads();
#pragma unroll
    for (int it = 0; it < 8; ++it) {
        int idx = t + it * 256;
        int jj = idx >> 6, d = idx & 63;
        float v = s[d][jj];
        g_embT [(j0 + jj) * E_DIM + d] = v;
        g_ebf16[(j0 + jj) * E_DIM + d] = __float2bfloat16(v);
    }
}

__global__ void __launch_bounds__(256) tr_x_kernel(const float* __restrict__ x) {
    __shared__ float s[64][33];
    int q0 = blockIdx.x * 32;
    int b = q0 >> 10, hw0 = q0 & 1023;
    int t = threadIdx.x;
    int gt = blockIdx.x * 256 + t;
    if (gt < N_QUERY) g_ncand[gt] = 0;       // graph replays need a fresh counter
#pragma unroll
    for (int it = 0; it < 8; ++it) {
        int idx = t + it * 256;
        int d = idx >> 5, qq = idx & 31;
        s[d][qq] = x[b * 65536 + d * 1024 + hw0 + qq];
    }
    __syncthreads();
#pragma unroll
    for (int it = 0; it < 8; ++it) {
        int idx = t + it * 256;
        int qq = idx >> 6, d = idx & 63;
        float v = s[d][qq];
        g_xq   [(q0 + qq) * E_DIM + d] = v;
        g_xbf16[(q0 + qq) * E_DIM + d] = __float2bfloat16(v);
    }
}

// ---------------- main HMMA + filter kernel ----------------
// dynamic smem: A 16KB | B0 16KB | B1 16KB | norms 32KB = 80KB
#define SM_A    0
#define SM_B0   16384
#define SM_B1   32768
#define SM_NORM 49152
#define SM_TOTAL 81920

__device__ __forceinline__ void issue_b_chunk(uint32_t smem_base, uint32_t bofs,
                                              int chunk, int tid) {
    const char* src = (const char*)(g_ebf16 + (size_t)chunk * NT * E_DIM);
#pragma unroll
    for (int it = 0; it < 4; ++it) {
        int i = tid + it * 256;                // 1024 x 16B
        uint32_t row = (uint32_t)(i >> 3), c = (uint32_t)(i & 7);
        uint32_t dst = smem_base + bofs + SWZ128(row * 128u + c * 16u);
        CP_ASYNC16(dst, src + (size_t)i * 16);
    }
}

__global__ void __launch_bounds__(256, 1) vq_mma_kernel() {
    extern __shared__ char smem[];
    const uint32_t smem_base = smem_u32(smem);
    float* snorm = (float*)(smem + SM_NORM);

    const int tid  = threadIdx.x;
    const int lane = tid & 31;
    const int wid  = tid >> 5;
    const int wm   = wid & 3;          // m-group: rows wm*32..+31
    const int wn   = wid >> 2;         // n-group: cols wn*64..+63
    const int m0   = wm * 32;
    const int n0   = wn * 64;
    const int q0   = blockIdx.x * MT;

    // ---- prologue: A tile (swizzled), norms, first two B chunks ----
    {
        const uint4* asrc = (const uint4*)(g_xbf16 + (size_t)q0 * E_DIM);
#pragma unroll
        for (int it = 0; it < 4; ++it) {
            int i = tid + it * 256;
            uint32_t row = (uint32_t)(i >> 3), c = (uint32_t)(i & 7);
            *(uint4*)(smem + SM_A + SWZ128(row * 128u + c * 16u)) = asrc[i];
        }
    }
    for (int i = tid; i < N_EMBED; i += 256) snorm[i] = g_norms[i];

    issue_b_chunk(smem_base, SM_B0, 0, tid); CP_COMMIT();
    issue_b_chunk(smem_base, SM_B1, 1, tid); CP_COMMIT();
    __syncthreads();

    // ---- A fragments: registers for the whole kernel ----
    uint32_t afrag[2][4][4];           // [mi][kstep][4]
#pragma unroll
    for (int mi = 0; mi < 2; ++mi)
#pragma unroll
        for (int ks = 0; ks < 4; ++ks) {
            int g = lane >> 3;
            uint32_t row = (uint32_t)(m0 + mi * 16 + (g & 1) * 8 + (lane & 7));
            uint32_t kb  = (uint32_t)(ks * 32 + ((g >> 1) & 1) * 16);
            uint32_t ad  = smem_base + SM_A + SWZ128(row * 128u + kb);
            LDSM_X4(afrag[mi][ks][0], afrag[mi][ks][1],
                    afrag[mi][ks][2], afrag[mi][ks][3], ad);
        }

    float runbest[4] = {FLT_MAX, FLT_MAX, FLT_MAX, FLT_MAX};
    const int rbase = q0 + m0 + (lane >> 2);   // +mi*16 +rr*8

    for (int c = 0; c < NCHUNK; ++c) {
        const uint32_t bofs = (c & 1) ? SM_B1 : SM_B0;
        CP_WAIT1();                    // chunk c resident
        __syncthreads();

        float acc[2][8][4];
#pragma unroll
        for (int mi = 0; mi < 2; ++mi)
#pragma unroll
            for (int nt = 0; nt < 8; ++nt)
#pragma unroll
                for (int e = 0; e < 4; ++e) acc[mi][nt][e] = 0.f;

#pragma unroll
        for (int ks = 0; ks < 4; ++ks) {
            uint32_t bfr[4][4];        // [pair of n-tiles][4]
#pragma unroll
            for (int np = 0; np < 4; ++np) {
                int g = lane >> 3;
                uint32_t row = (uint32_t)(n0 + np * 16 + ((g >> 1) & 1) * 8 + (lane & 7));
                uint32_t kb  = (uint32_t)(ks * 32 + (g & 1) * 16);
                uint32_t ad  = smem_base + bofs + SWZ128(row * 128u + kb);
                LDSM_X4(bfr[np][0], bfr[np][1], bfr[np][2], bfr[np][3], ad);
            }
#pragma unroll
            for (int mi = 0; mi < 2; ++mi)
#pragma unroll
                for (int nt = 0; nt < 8; ++nt)
                    mma16816(acc[mi][nt], afrag[mi][ks], &bfr[nt >> 1][(nt & 1) * 2]);
        }
        __syncthreads();               // everyone done reading buf before refill

        if (c + 2 < NCHUNK) issue_b_chunk(smem_base, bofs, c + 2, tid);
        CP_COMMIT();                   // keep group count aligned (empty ok)

        // ---- epilogue: filter on register accumulators ----
        const int cbase = c * NT;
        float nrm[16];
#pragma unroll
        for (int nt = 0; nt < 8; ++nt) {
            nrm[nt * 2]     = snorm[cbase + n0 + nt * 8 + 2 * (lane & 3)];
            nrm[nt * 2 + 1] = snorm[cbase + n0 + nt * 8 + 2 * (lane & 3) + 1];
        }
#pragma unroll
        for (int mi = 0; mi < 2; ++mi)
#pragma unroll
            for (int rr = 0; rr < 2; ++rr) {
                const int q = rbase + mi * 16 + rr * 8;
                float rb = runbest[mi * 2 + rr];
#pragma unroll
                for (int nt = 0; nt < 8; ++nt)
#pragma unroll
                    for (int e = 0; e < 2; ++e) {
                        float score = fmaf(-2.f, acc[mi][nt][rr * 2 + e], nrm[nt * 2 + e]);
                        if (score < rb + MARGIN) {
                            int pos = atomicAdd(&g_ncand[q], 1);
                            if (pos < CAND_MAX)
                                g_cand[q * CAND_MAX + pos] =
                                    cbase + n0 + nt * 8 + 2 * (lane & 3) + e;
                            rb = fminf(rb, score);
                        }
                    }
                runbest[mi * 2 + rr] = rb;
            }
        // tighten running minima across the 4 lanes sharing each query row
#pragma unroll
        for (int s = 0; s < 4; ++s) {
            runbest[s] = fminf(runbest[s], __shfl_xor_sync(0xFFFFFFFFu, runbest[s], 1));
            runbest[s] = fminf(runbest[s], __shfl_xor_sync(0xFFFFFFFFu, runbest[s], 2));
        }
    }
}

// ---------------- exact fp32 rescore + gather ----------------
__global__ void __launch_bounds__(256) rescore_kernel(float* __restrict__ out) {
    const int wid = threadIdx.x >> 5, lid = threadIdx.x & 31;
    const int q = blockIdx.x * 8 + wid;

    const float x0 = g_xq[q * E_DIM + lid];
    const float x1 = g_xq[q * E_DIM + 32 + lid];
    const int nc = g_ncand[q];

    float best = FLT_MAX;
    int bj = N_EMBED;
    if (nc <= CAND_MAX) {
        for (int i = 0; i < nc; ++i) {
            int j = g_cand[q * CAND_MAX + i];
            float e0 = g_embT[j * E_DIM + lid];
            float e1 = g_embT[j * E_DIM + 32 + lid];
            float p = fmaf(x0, e0, x1 * e1);
#pragma unroll
            for (int o = 16; o > 0; o >>= 1) p += __shfl_xor_sync(0xFFFFFFFFu, p, o);
            float score = fmaf(-2.f, p, g_norms[j]);
            if (score < best || (score == best && j < bj)) { best = score; bj = j; }
        }
    } else {
        // candidate overflow (should be ~never): exact full scan
        for (int j = 0; j < N_EMBED; ++j) {
            float e0 = g_embT[j * E_DIM + lid];
            float e1 = g_embT[j * E_DIM + 32 + lid];
            float p = fmaf(x0, e0, x1 * e1);
#pragma unroll
            for (int o = 16; o > 0; o >>= 1) p += __shfl_xor_sync(0xFFFFFFFFu, p, o);
            float score = fmaf(-2.f, p, g_norms[j]);
            if (score < best) { best = score; bj = j; }
        }
    }
    out[q * E_DIM + lid]      = g_embT[bj * E_DIM + lid];
    out[q * E_DIM + 32 + lid] = g_embT[bj * E_DIM + 32 + lid];
}

// ---------------- launch ----------------
extern "C" void kernel_launch(void* const* d_in, const int* in_sizes, int n_in,
                              void* d_out, int out_size) {
    const float* x     = (const float*)d_in[0];   // [16,64,32,32]
    const float* embed = (const float*)d_in[1];   // [64,8192]
    float* out = (float*)d_out;                   // [16,32,32,64]

    norms_kernel<<<N_EMBED / 256, 256>>>(embed);
    tr_e_kernel<<<N_EMBED / 32, 256>>>(embed);
    tr_x_kernel<<<N_QUERY / 32, 256>>>(x);

    cudaFuncSetAttribute(vq_mma_kernel, cudaFuncAttributeMaxDynamicSharedMemorySize, SM_TOTAL);
    vq_mma_kernel<<<N_QUERY / MT, 256, SM_TOTAL>>>();

    rescore_kernel<<<N_QUERY / 8, 256>>>(out);
}

// round 7
// speedup vs baseline: 1.8103x; 1.1458x over previous
#include <cuda_runtime.h>
#include <cuda_bf16.h>
#include <cfloat>
#include <cstdint>

#define N_EMBED  8192
#define E_DIM    64
#define N_QUERY  16384
#define MT       128                 // queries per CTA
#define NT       128                 // codes per chunk
#define NCHUNK   (N_EMBED / NT)      // 64
#define NTHREADS 512
#define NSTAGE   4
#define CAND_MAX 160
#define MARGIN   0.5f

// ---------------- global scratch ----------------
__device__ __align__(16) float          g_norms[N_EMBED];
__device__ __align__(16) float          g_embT [N_EMBED * E_DIM];   // [code][k] fp32 (exact)
__device__ __align__(16) __nv_bfloat16  g_ebf16[N_EMBED * E_DIM];   // [code][k] bf16
__device__ __align__(16) float          g_xq   [N_QUERY * E_DIM];   // [q][k] fp32
__device__ __align__(16) __nv_bfloat16  g_xbf16[N_QUERY * E_DIM];   // [q][k] bf16
__device__ int            g_cand [N_QUERY * CAND_MAX];
__device__ int            g_ncand[N_QUERY];

// ---------------- PTX helpers (family-safe: sm_80+) ----------------
__device__ __forceinline__ uint32_t smem_u32(const void* p) {
    uint32_t a;
    asm("{ .reg .u64 t; cvta.to.shared.u64 t, %1; cvt.u32.u64 %0, t; }" : "=r"(a) : "l"(p));
    return a;
}
#define SWZ128(o) ((o) ^ (((o) >> 3) & 0x70))

#define CP_ASYNC16(dst, src) \
    asm volatile("cp.async.cg.shared.global [%0], [%1], 16;" :: "r"(dst), "l"(src) : "memory")
#define CP_COMMIT() asm volatile("cp.async.commit_group;" ::: "memory")
#define CP_WAIT2()  asm volatile("cp.async.wait_group 2;" ::: "memory")

#define LDSM_X4(r0, r1, r2, r3, addr) \
    asm volatile("ldmatrix.sync.aligned.m8n8.x4.shared.b16 {%0,%1,%2,%3}, [%4];" \
                 : "=r"(r0), "=r"(r1), "=r"(r2), "=r"(r3) : "r"(addr))

__device__ __forceinline__ void mma16816(float* c, const uint32_t* a, const uint32_t* b) {
    asm volatile(
        "mma.sync.aligned.m16n8k16.row.col.f32.bf16.bf16.f32 "
        "{%0,%1,%2,%3}, {%4,%5,%6,%7}, {%8,%9}, {%0,%1,%2,%3};"
        : "+f"(c[0]), "+f"(c[1]), "+f"(c[2]), "+f"(c[3])
        : "r"(a[0]), "r"(a[1]), "r"(a[2]), "r"(a[3]), "r"(b[0]), "r"(b[1]));
}

// ---------------- fused prep kernel ----------------
// blocks [0,256):   embed transpose -> g_embT / g_ebf16   (32 codes each)
// blocks [256,768): x transpose     -> g_xq / g_xbf16     (32 queries each) + ncand reset
// blocks [768,800): code norms      -> g_norms            (256 codes each)
__global__ void __launch_bounds__(256) prep_kernel(const float* __restrict__ x,
                                                   const float* __restrict__ embed) {
    const int bid = blockIdx.x;
    const int t = threadIdx.x;
    if (bid < 256) {
        __shared__ float s[64][33];
        int j0 = bid * 32;
#pragma unroll
        for (int it = 0; it < 8; ++it) {
            int idx = t + it * 256;
            int d = idx >> 5, jj = idx & 31;
            s[d][jj] = embed[d * N_EMBED + j0 + jj];
        }
        __syncthreads();
#pragma unroll
        for (int it = 0; it < 8; ++it) {
            int idx = t + it * 256;
            int jj = idx >> 6, d = idx & 63;
            float v = s[d][jj];
            g_embT [(j0 + jj) * E_DIM + d] = v;
            g_ebf16[(j0 + jj) * E_DIM + d] = __float2bfloat16(v);
        }
    } else if (bid < 768) {
        __shared__ float s[64][33];
        int q0 = (bid - 256) * 32;
        int gt = (bid - 256) * 256 + t;
        if (gt < N_QUERY) g_ncand[gt] = 0;       // fresh counters every graph replay
        int b = q0 >> 10, hw0 = q0 & 1023;
#pragma unroll
        for (int it = 0; it < 8; ++it) {
            int idx = t + it * 256;
            int d = idx >> 5, qq = idx & 31;
            s[d][qq] = x[b * 65536 + d * 1024 + hw0 + qq];
        }
        __syncthreads();
#pragma unroll
        for (int it = 0; it < 8; ++it) {
            int idx = t + it * 256;
            int qq = idx >> 6, d = idx & 63;
            float v = s[d][qq];
            g_xq   [(q0 + qq) * E_DIM + d] = v;
            g_xbf16[(q0 + qq) * E_DIM + d] = __float2bfloat16(v);
        }
    } else {
        int j = (bid - 768) * 256 + t;
        float s = 0.f;
#pragma unroll
        for (int d = 0; d < E_DIM; ++d) {
            float v = embed[d * N_EMBED + j];
            s = fmaf(v, v, s);
        }
        g_norms[j] = s;
    }
}

// ---------------- main HMMA + filter kernel ----------------
// dynamic smem: A 16KB | B ring 4x16KB | norms 32KB = 112KB
#define SM_A     0
#define SM_B     16384
#define SM_NORM  (16384 + NSTAGE * 16384)
#define SM_TOTAL (SM_NORM + 32768)

__device__ __forceinline__ void issue_b_chunk(uint32_t smem_base, uint32_t bofs,
                                              int chunk, int tid) {
    const char* src = (const char*)(g_ebf16 + (size_t)chunk * NT * E_DIM);
#pragma unroll
    for (int it = 0; it < (NT * 8) / NTHREADS; ++it) {
        int i = tid + it * NTHREADS;           // 1024 x 16B
        uint32_t row = (uint32_t)(i >> 3), cc = (uint32_t)(i & 7);
        uint32_t dst = smem_base + bofs + SWZ128(row * 128u + cc * 16u);
        CP_ASYNC16(dst, src + (size_t)i * 16);
    }
}

__global__ void __launch_bounds__(NTHREADS, 1) vq_mma_kernel() {
    extern __shared__ char smem[];
    const uint32_t smem_base = smem_u32(smem);
    float* snorm = (float*)(smem + SM_NORM);

    const int tid  = threadIdx.x;
    const int lane = tid & 31;
    const int wid  = tid >> 5;        // 16 warps
    const int m0   = (wid & 3) * 32;  // m-group
    const int n0   = (wid >> 2) * 32; // n-group (4 groups x 32 = 128)
    const int q0   = blockIdx.x * MT;

    // ---- prologue: A tile (swizzled), norms, first three B chunks ----
    {
        const uint4* asrc = (const uint4*)(g_xbf16 + (size_t)q0 * E_DIM);
#pragma unroll
        for (int it = 0; it < (MT * 8) / NTHREADS; ++it) {
            int i = tid + it * NTHREADS;
            uint32_t row = (uint32_t)(i >> 3), cc = (uint32_t)(i & 7);
            *(uint4*)(smem + SM_A + SWZ128(row * 128u + cc * 16u)) = asrc[i];
        }
    }
    {
        const float4* nsrc = (const float4*)g_norms;
        float4* ndst = (float4*)snorm;
#pragma unroll
        for (int it = 0; it < (N_EMBED / 4) / NTHREADS; ++it)
            ndst[tid + it * NTHREADS] = nsrc[tid + it * NTHREADS];
    }
    issue_b_chunk(smem_base, SM_B + 0 * 16384, 0, tid); CP_COMMIT();
    issue_b_chunk(smem_base, SM_B + 1 * 16384, 1, tid); CP_COMMIT();
    issue_b_chunk(smem_base, SM_B + 2 * 16384, 2, tid); CP_COMMIT();
    __syncthreads();

    // ---- A fragments: registers for the whole kernel ----
    uint32_t afrag[2][4][4];           // [mi][kstep][4]
#pragma unroll
    for (int mi = 0; mi < 2; ++mi)
#pragma unroll
        for (int ks = 0; ks < 4; ++ks) {
            int g = lane >> 3;
            uint32_t row = (uint32_t)(m0 + mi * 16 + (g & 1) * 8 + (lane & 7));
            uint32_t kb  = (uint32_t)(ks * 32 + ((g >> 1) & 1) * 16);
            uint32_t ad  = smem_base + SM_A + SWZ128(row * 128u + kb);
            LDSM_X4(afrag[mi][ks][0], afrag[mi][ks][1],
                    afrag[mi][ks][2], afrag[mi][ks][3], ad);
        }

    float runbest[4] = {FLT_MAX, FLT_MAX, FLT_MAX, FLT_MAX};
    const int rbase = q0 + m0 + (lane >> 2);   // +mi*16 +rr*8

    for (int c = 0; c < NCHUNK; ++c) {
        const uint32_t bofs = SM_B + (uint32_t)(c & (NSTAGE - 1)) * 16384u;
        CP_WAIT2();                    // groups 0..c complete -> chunk c resident
        __syncthreads();               // the ONLY barrier per chunk

        // refill slot (c+3)&3 = chunk (c-1)'s slot; its readers all passed the barrier
        if (c + 3 < NCHUNK)
            issue_b_chunk(smem_base, SM_B + (uint32_t)((c + 3) & (NSTAGE - 1)) * 16384u,
                          c + 3, tid);
        CP_COMMIT();                   // always commit: keeps wait_group accounting exact

        float acc[2][4][4];
#pragma unroll
        for (int mi = 0; mi < 2; ++mi)
#pragma unroll
            for (int nt = 0; nt < 4; ++nt)
#pragma unroll
                for (int e = 0; e < 4; ++e) acc[mi][nt][e] = 0.f;

#pragma unroll
        for (int ks = 0; ks < 4; ++ks) {
            uint32_t bfr[2][4];
#pragma unroll
            for (int np = 0; np < 2; ++np) {
                int g = lane >> 3;
                uint32_t row = (uint32_t)(n0 + np * 16 + ((g >> 1) & 1) * 8 + (lane & 7));
                uint32_t kb  = (uint32_t)(ks * 32 + (g & 1) * 16);
                uint32_t ad  = smem_base + bofs + SWZ128(row * 128u + kb);
                LDSM_X4(bfr[np][0], bfr[np][1], bfr[np][2], bfr[np][3], ad);
            }
#pragma unroll
            for (int mi = 0; mi < 2; ++mi)
#pragma unroll
                for (int nt = 0; nt < 4; ++nt)
                    mma16816(acc[mi][nt], afrag[mi][ks], &bfr[nt >> 1][(nt & 1) * 2]);
        }

        // ---- epilogue: filter on register accumulators ----
        const int cbase = c * NT;
        float nrm[8];
#pragma unroll
        for (int nt = 0; nt < 4; ++nt) {
            nrm[nt * 2]     = snorm[cbase + n0 + nt * 8 + 2 * (lane & 3)];
            nrm[nt * 2 + 1] = snorm[cbase + n0 + nt * 8 + 2 * (lane & 3) + 1];
        }
#pragma unroll
        for (int mi = 0; mi < 2; ++mi)
#pragma unroll
            for (int rr = 0; rr < 2; ++rr) {
                const int q = rbase + mi * 16 + rr * 8;
                float rb = runbest[mi * 2 + rr];
#pragma unroll
                for (int nt = 0; nt < 4; ++nt)
#pragma unroll
                    for (int e = 0; e < 2; ++e) {
                        float score = fmaf(-2.f, acc[mi][nt][rr * 2 + e], nrm[nt * 2 + e]);
                        if (score < rb + MARGIN) {
                            int pos = atomicAdd(&g_ncand[q], 1);
                            if (pos < CAND_MAX)
                                g_cand[q * CAND_MAX + pos] =
                                    cbase + n0 + nt * 8 + 2 * (lane & 3) + e;
                            rb = fminf(rb, score);
                        }
                    }
                runbest[mi * 2 + rr] = rb;
            }
        // tighten running minima across the 4 lanes sharing each query row
#pragma unroll
        for (int s = 0; s < 4; ++s) {
            runbest[s] = fminf(runbest[s], __shfl_xor_sync(0xFFFFFFFFu, runbest[s], 1));
            runbest[s] = fminf(runbest[s], __shfl_xor_sync(0xFFFFFFFFu, runbest[s], 2));
        }
    }
}

// ---------------- exact fp32 rescore + gather ----------------
__global__ void __launch_bounds__(256) rescore_kernel(float* __restrict__ out) {
    const int wid = threadIdx.x >> 5, lid = threadIdx.x & 31;
    const int q = blockIdx.x * 8 + wid;

    const float x0 = g_xq[q * E_DIM + lid];
    const float x1 = g_xq[q * E_DIM + 32 + lid];
    const int nc = g_ncand[q];

    float best = FLT_MAX;
    int bj = N_EMBED;
    if (nc <= CAND_MAX) {
        for (int i = 0; i < nc; ++i) {
            int j = g_cand[q * CAND_MAX + i];
            float e0 = g_embT[j * E_DIM + lid];
            float e1 = g_embT[j * E_DIM + 32 + lid];
            float p = fmaf(x0, e0, x1 * e1);
#pragma unroll
            for (int o = 16; o > 0; o >>= 1) p += __shfl_xor_sync(0xFFFFFFFFu, p, o);
            float score = fmaf(-2.f, p, g_norms[j]);
            if (score < best || (score == best && j < bj)) { best = score; bj = j; }
        }
    } else {
        // candidate overflow (should be ~never): exact full scan
        for (int j = 0; j < N_EMBED; ++j) {
            float e0 = g_embT[j * E_DIM + lid];
            float e1 = g_embT[j * E_DIM + 32 + lid];
            float p = fmaf(x0, e0, x1 * e1);
#pragma unroll
            for (int o = 16; o > 0; o >>= 1) p += __shfl_xor_sync(0xFFFFFFFFu, p, o);
            float score = fmaf(-2.f, p, g_norms[j]);
            if (score < best) { best = score; bj = j; }
        }
    }
    out[q * E_DIM + lid]      = g_embT[bj * E_DIM + lid];
    out[q * E_DIM + 32 + lid] = g_embT[bj * E_DIM + 32 + lid];
}

// ---------------- launch ----------------
extern "C" void kernel_launch(void* const* d_in, const int* in_sizes, int n_in,
                              void* d_out, int out_size) {
    const float* x     = (const float*)d_in[0];   // [16,64,32,32]
    const float* embed = (const float*)d_in[1];   // [64,8192]
    float* out = (float*)d_out;                   // [16,32,32,64]

    prep_kernel<<<800, 256>>>(x, embed);

    cudaFuncSetAttribute(vq_mma_kernel, cudaFuncAttributeMaxDynamicSharedMemorySize, SM_TOTAL);
    vq_mma_kernel<<<N_QUERY / MT, NTHREADS, SM_TOTAL>>>();

    rescore_kernel<<<N_QUERY / 8, 256>>>(out);
}